// round 2
// baseline (speedup 1.0000x reference)
#include <cuda_runtime.h>

#define NN 10000
#define NE 320000
#define DH 256
#define NC 40

// Static scratch (allowed): ping-pong feature buffers + clean int32 edge index.
__device__ __align__(16) float4 g_bufA[NN * DH / 4];
__device__ __align__(16) float4 g_bufB[NN * DH / 4];
__device__ int g_idx[2 * NE];   // [0,NE) = src, [NE,2NE) = dst
__device__ int g_is64;

// ---------------------------------------------------------------------------
// Edge-index dtype detection: if the buffer is int64 (values < 2^31), every
// odd int32 word is zero. 64 samples of genuine int32 data being all zero is
// probability ~0. Single thread; trivial cost.
// ---------------------------------------------------------------------------
__global__ void detect_dtype(const int* __restrict__ p)
{
    if (blockIdx.x == 0 && threadIdx.x == 0) {
        int any_nonzero = 0;
        for (int i = 0; i < 64; i++)
            any_nonzero |= p[2 * i + 1];
        g_is64 = (any_nonzero == 0) ? 1 : 0;
    }
}

__global__ void convert_idx(const void* __restrict__ p)
{
    const int i = blockIdx.x * blockDim.x + threadIdx.x;
    if (i >= 2 * NE) return;
    int v;
    if (g_is64) v = (int)((const long long*)p)[i];
    else        v = ((const int*)p)[i];
    // clamp for safety (should always be in range)
    g_idx[i] = min(max(v, 0), NN - 1);
}

// ---------------------------------------------------------------------------
// Tiled SGEMM: C[M,N] = act(A)[M,K] @ B[K,N] + bias   (act = ReLU if RELU_IN)
// 64x64 tile, BK=16, 256 threads, 4x4 per thread. K multiple of 16.
// ---------------------------------------------------------------------------
template<bool RELU_IN>
__global__ void gemm64(const float* __restrict__ A, const float* __restrict__ B,
                       const float* __restrict__ bias, float* __restrict__ C,
                       int M, int N, int K)
{
    __shared__ float As[16][64];
    __shared__ float Bs[16][64];
    const int tid = threadIdx.x;
    const int ty = tid >> 4, tx = tid & 15;
    const int m0 = blockIdx.y * 64;
    const int n0 = blockIdx.x * 64;

    float acc[4][4];
#pragma unroll
    for (int i = 0; i < 4; i++)
#pragma unroll
        for (int j = 0; j < 4; j++) acc[i][j] = 0.f;

    const int la = tid * 4;
    const int ar = la >> 4, ac = la & 15;   // A-tile: row 0..63, col 0..15 (x4)
    const int br = la >> 6, bc = la & 63;   // B-tile: row 0..15, col 0..63 (x4)
    const int grow = m0 + ar;
    const int gcol = n0 + bc;

    for (int k0 = 0; k0 < K; k0 += 16) {
        float4 va = make_float4(0.f, 0.f, 0.f, 0.f);
        if (grow < M)
            va = *reinterpret_cast<const float4*>(&A[(size_t)grow * K + k0 + ac]);
        if (RELU_IN) {
            va.x = fmaxf(va.x, 0.f); va.y = fmaxf(va.y, 0.f);
            va.z = fmaxf(va.z, 0.f); va.w = fmaxf(va.w, 0.f);
        }
        As[ac + 0][ar] = va.x; As[ac + 1][ar] = va.y;
        As[ac + 2][ar] = va.z; As[ac + 3][ar] = va.w;

        float4 vb = make_float4(0.f, 0.f, 0.f, 0.f);
        if (gcol < N)  // N is a multiple of 4 (256 or 40), float4 is all-or-nothing
            vb = *reinterpret_cast<const float4*>(&B[(size_t)(k0 + br) * N + gcol]);
        Bs[br][bc + 0] = vb.x; Bs[br][bc + 1] = vb.y;
        Bs[br][bc + 2] = vb.z; Bs[br][bc + 3] = vb.w;

        __syncthreads();
#pragma unroll
        for (int k = 0; k < 16; k++) {
            float a[4], b[4];
#pragma unroll
            for (int i = 0; i < 4; i++) a[i] = As[k][ty * 4 + i];
#pragma unroll
            for (int j = 0; j < 4; j++) b[j] = Bs[k][tx * 4 + j];
#pragma unroll
            for (int i = 0; i < 4; i++)
#pragma unroll
                for (int j = 0; j < 4; j++)
                    acc[i][j] += a[i] * b[j];
        }
        __syncthreads();
    }

#pragma unroll
    for (int i = 0; i < 4; i++) {
        int row = m0 + ty * 4 + i;
        if (row >= M) continue;
#pragma unroll
        for (int j = 0; j < 4; j++) {
            int col = n0 + tx * 4 + j;
            if (col < N)
                C[(size_t)row * N + col] = acc[i][j] + bias[col];
        }
    }
}

// ---------------------------------------------------------------------------
// Edge scatter-sum: out[dst] += h[src], CH float4 chunks per edge.
// One thread per (edge, chunk). Vector float4 atomicAdd (sm_90+) -> REDG.128.
// ---------------------------------------------------------------------------
template<int CH>
__global__ void scatter_add(const float4* __restrict__ h,
                            float4* __restrict__ out)
{
    const int t = blockIdx.x * blockDim.x + threadIdx.x;
    if (t >= NE * CH) return;
    const int e = t / CH;
    const int c = t - e * CH;
    const int src = g_idx[e];
    const int dst = g_idx[NE + e];
    const float4 v = h[(size_t)src * CH + c];
    atomicAdd(&out[(size_t)dst * CH + c], v);
}

__global__ void zero4(float4* __restrict__ p, int n)
{
    const int i = blockIdx.x * blockDim.x + threadIdx.x;
    if (i < n) p[i] = make_float4(0.f, 0.f, 0.f, 0.f);
}

__global__ void relu_ip(float* __restrict__ p, int n)
{
    const int i = blockIdx.x * blockDim.x + threadIdx.x;
    if (i < n) p[i] = fmaxf(p[i], 0.f);
}

// ---------------------------------------------------------------------------
extern "C" void kernel_launch(void* const* d_in, const int* in_sizes, int n_in,
                              void* d_out, int out_size)
{
    const float* x  = (const float*)d_in[0];
    const void*  ei = d_in[1];
    const float* W1 = (const float*)d_in[2];
    const float* b1 = (const float*)d_in[3];
    const float* W2 = (const float*)d_in[4];
    const float* b2 = (const float*)d_in[5];
    const float* W3 = (const float*)d_in[6];
    const float* b3 = (const float*)d_in[7];
    float* out = (float*)d_out;

    float4 *bufA, *bufB;
    cudaGetSymbolAddress((void**)&bufA, g_bufA);
    cudaGetSymbolAddress((void**)&bufB, g_bufB);

    const dim3 blk(256);
    const dim3 gHid((DH + 63) / 64, (NN + 63) / 64);  // (4, 157)
    const dim3 gCls((NC + 63) / 64, (NN + 63) / 64);  // (1, 157)

    const int n4   = NN * DH / 4;   // 640000 float4
    const int out4 = NN * NC / 4;   // 100000 float4

    // Edge index: detect int32 vs int64, materialize clean int32 src/dst.
    detect_dtype<<<1, 32>>>((const int*)ei);
    convert_idx<<<(2 * NE + 255) / 256, blk>>>(ei);

    // Layer 1: h = x @ W1 + b1 ; agg = scatter(h)
    gemm64<false><<<gHid, blk>>>(x, W1, b1, (float*)bufB, NN, DH, DH);
    zero4<<<(n4 + 255) / 256, blk>>>(bufA, n4);
    scatter_add<DH / 4><<<(NE * (DH / 4) + 255) / 256, blk>>>(bufB, bufA);

    // Layer 2: h = relu(agg) @ W2 + b2 ; agg = scatter(h)
    gemm64<true><<<gHid, blk>>>((const float*)bufA, W2, b2, (float*)bufB, NN, DH, DH);
    zero4<<<(n4 + 255) / 256, blk>>>(bufA, n4);
    scatter_add<DH / 4><<<(NE * (DH / 4) + 255) / 256, blk>>>(bufB, bufA);

    // Layer 3: h = relu(agg) @ W3 + b3 ; out = relu(scatter(h))
    gemm64<true><<<gCls, blk>>>((const float*)bufA, W3, b3, (float*)bufB, NN, NC, DH);
    zero4<<<(out4 + 255) / 256, blk>>>((float4*)out, out4);
    scatter_add<NC / 4><<<(NE * (NC / 4) + 255) / 256, blk>>>(bufB, (float4*)out);
    relu_ip<<<(NN * NC + 255) / 256, blk>>>(out, NN * NC);
}

// round 4
// speedup vs baseline: 1.1987x; 1.1987x over previous
#include <cuda_runtime.h>

#define NN 10000
#define NE 320000
#define DH 256
#define NC 40

// Static scratch (allowed).
__device__ __align__(16) float4 g_bufA[NN * DH / 4];
__device__ __align__(16) float4 g_bufB[NN * DH / 4];
__device__ int g_idx[2 * NE];      // [0,NE)=src, [NE,2NE)=dst (clean int32)
__device__ int g_deg[NN];
__device__ int g_off[NN + 1];
__device__ int g_cur[NN];
__device__ int g_esrc[NE];         // src ids grouped by dst (CSR payload)
__device__ int g_is64;

// ---------------------------------------------------------------------------
// Edge-index dtype detection (int64 vs int32): for int64 values < 2^31 every
// odd int32 word is zero.
// ---------------------------------------------------------------------------
__global__ void detect_dtype(const int* __restrict__ p)
{
    if (blockIdx.x == 0 && threadIdx.x == 0) {
        int any_nonzero = 0;
        for (int i = 0; i < 64; i++)
            any_nonzero |= p[2 * i + 1];
        g_is64 = (any_nonzero == 0) ? 1 : 0;
    }
}

// Convert edge index to clean int32 (clamped) AND zero the degree histogram.
__global__ void convert_idx(const void* __restrict__ p)
{
    const int i = blockIdx.x * blockDim.x + threadIdx.x;
    if (i < NN) g_deg[i] = 0;
    if (i >= 2 * NE) return;
    int v;
    if (g_is64) v = (int)((const long long*)p)[i];
    else        v = ((const int*)p)[i];
    g_idx[i] = min(max(v, 0), NN - 1);
}

__global__ void hist_dst()
{
    const int e = blockIdx.x * blockDim.x + threadIdx.x;
    if (e < NE) atomicAdd(&g_deg[g_idx[NE + e]], 1);
}

// Single-block exclusive scan over NN degrees -> g_off, g_cur.
__global__ void scan_deg()
{
    __shared__ int s[1024];
    __shared__ int carry_s;
    if (threadIdx.x == 0) carry_s = 0;
    __syncthreads();
    for (int c = 0; c < NN; c += 1024) {
        const int i = c + threadIdx.x;
        const int v = (i < NN) ? g_deg[i] : 0;
        s[threadIdx.x] = v;
        __syncthreads();
#pragma unroll
        for (int d = 1; d < 1024; d <<= 1) {
            int t = (threadIdx.x >= d) ? s[threadIdx.x - d] : 0;
            __syncthreads();
            s[threadIdx.x] += t;
            __syncthreads();
        }
        if (i < NN) {
            const int excl = carry_s + s[threadIdx.x] - v;
            g_off[i] = excl;
            g_cur[i] = excl;
        }
        __syncthreads();
        if (threadIdx.x == 1023) carry_s += s[1023];
        __syncthreads();
    }
    if (threadIdx.x == 0) g_off[NN] = carry_s;
}

__global__ void fill_csr()
{
    const int e = blockIdx.x * blockDim.x + threadIdx.x;
    if (e >= NE) return;
    const int dst = g_idx[NE + e];
    const int pos = atomicAdd(&g_cur[dst], 1);
    g_esrc[pos] = g_idx[e];
}

// ---------------------------------------------------------------------------
// Tiled SGEMM: C[M,N] = act(A)[M,K] @ B[K,N] + bias   (act = ReLU if RELU_IN)
// 64x64 tile, BK=16, 256 threads, 4x4 per thread. K multiple of 16.
// ---------------------------------------------------------------------------
template<bool RELU_IN>
__global__ void gemm64(const float* __restrict__ A, const float* __restrict__ B,
                       const float* __restrict__ bias, float* __restrict__ C,
                       int M, int N, int K)
{
    __shared__ float As[16][64];
    __shared__ float Bs[16][64];
    const int tid = threadIdx.x;
    const int ty = tid >> 4, tx = tid & 15;
    const int m0 = blockIdx.y * 64;
    const int n0 = blockIdx.x * 64;

    float acc[4][4];
#pragma unroll
    for (int i = 0; i < 4; i++)
#pragma unroll
        for (int j = 0; j < 4; j++) acc[i][j] = 0.f;

    const int la = tid * 4;
    const int ar = la >> 4, ac = la & 15;
    const int br = la >> 6, bc = la & 63;
    const int grow = m0 + ar;
    const int gcol = n0 + bc;

    for (int k0 = 0; k0 < K; k0 += 16) {
        float4 va = make_float4(0.f, 0.f, 0.f, 0.f);
        if (grow < M)
            va = *reinterpret_cast<const float4*>(&A[(size_t)grow * K + k0 + ac]);
        if (RELU_IN) {
            va.x = fmaxf(va.x, 0.f); va.y = fmaxf(va.y, 0.f);
            va.z = fmaxf(va.z, 0.f); va.w = fmaxf(va.w, 0.f);
        }
        As[ac + 0][ar] = va.x; As[ac + 1][ar] = va.y;
        As[ac + 2][ar] = va.z; As[ac + 3][ar] = va.w;

        float4 vb = make_float4(0.f, 0.f, 0.f, 0.f);
        if (gcol < N)
            vb = *reinterpret_cast<const float4*>(&B[(size_t)(k0 + br) * N + gcol]);
        Bs[br][bc + 0] = vb.x; Bs[br][bc + 1] = vb.y;
        Bs[br][bc + 2] = vb.z; Bs[br][bc + 3] = vb.w;

        __syncthreads();
#pragma unroll
        for (int k = 0; k < 16; k++) {
            float a[4], b[4];
#pragma unroll
            for (int i = 0; i < 4; i++) a[i] = As[k][ty * 4 + i];
#pragma unroll
            for (int j = 0; j < 4; j++) b[j] = Bs[k][tx * 4 + j];
#pragma unroll
            for (int i = 0; i < 4; i++)
#pragma unroll
                for (int j = 0; j < 4; j++)
                    acc[i][j] += a[i] * b[j];
        }
        __syncthreads();
    }

#pragma unroll
    for (int i = 0; i < 4; i++) {
        int row = m0 + ty * 4 + i;
        if (row >= M) continue;
#pragma unroll
        for (int j = 0; j < 4; j++) {
            int col = n0 + tx * 4 + j;
            if (col < N)
                C[(size_t)row * N + col] = acc[i][j] + bias[col];
        }
    }
}

// ---------------------------------------------------------------------------
// Pull-mode aggregation, D=256: one block per node, thread tid owns feature
// column tid. Edges staged through shared in chunks of 256. No atomics.
// ---------------------------------------------------------------------------
__global__ void agg256(const float* __restrict__ h, float* __restrict__ out)
{
    __shared__ int s_idx[256];
    const int node = blockIdx.x;
    const int tid = threadIdx.x;
    const int beg = g_off[node], end = g_off[node + 1];

    float acc = 0.f;
    for (int c = beg; c < end; c += 256) {
        const int n = min(256, end - c);
        if (tid < n) s_idx[tid] = g_esrc[c + tid];
        __syncthreads();
        int j = 0;
        for (; j + 4 <= n; j += 4) {
            const int s0 = s_idx[j + 0], s1 = s_idx[j + 1];
            const int s2 = s_idx[j + 2], s3 = s_idx[j + 3];
            const float v0 = h[(size_t)s0 * DH + tid];
            const float v1 = h[(size_t)s1 * DH + tid];
            const float v2 = h[(size_t)s2 * DH + tid];
            const float v3 = h[(size_t)s3 * DH + tid];
            acc += v0 + v1 + v2 + v3;
        }
        for (; j < n; j++)
            acc += h[(size_t)s_idx[j] * DH + tid];
        __syncthreads();
    }
    out[(size_t)node * DH + tid] = acc;
}

// ---------------------------------------------------------------------------
// Pull-mode aggregation, D=40 (+ReLU): 4 nodes per 256-thread block,
// 64 threads per node (24 idle). Output is the final result.
// ---------------------------------------------------------------------------
__global__ void agg40_relu(const float* __restrict__ h, float* __restrict__ out)
{
    const int tid = threadIdx.x;
    const int node = blockIdx.x * 4 + (tid >> 6);
    const int f = tid & 63;
    if (node >= NN || f >= NC) return;
    const int beg = g_off[node], end = g_off[node + 1];

    float acc = 0.f;
    int e = beg;
    for (; e + 4 <= end; e += 4) {
        const int s0 = g_esrc[e + 0], s1 = g_esrc[e + 1];
        const int s2 = g_esrc[e + 2], s3 = g_esrc[e + 3];
        const float v0 = h[(size_t)s0 * NC + f];
        const float v1 = h[(size_t)s1 * NC + f];
        const float v2 = h[(size_t)s2 * NC + f];
        const float v3 = h[(size_t)s3 * NC + f];
        acc += v0 + v1 + v2 + v3;
    }
    for (; e < end; e++)
        acc += h[(size_t)g_esrc[e] * NC + f];
    out[(size_t)node * NC + f] = fmaxf(acc, 0.f);
}

// ---------------------------------------------------------------------------
extern "C" void kernel_launch(void* const* d_in, const int* in_sizes, int n_in,
                              void* d_out, int out_size)
{
    const float* x  = (const float*)d_in[0];
    const void*  ei = d_in[1];
    const float* W1 = (const float*)d_in[2];
    const float* b1 = (const float*)d_in[3];
    const float* W2 = (const float*)d_in[4];
    const float* b2 = (const float*)d_in[5];
    const float* W3 = (const float*)d_in[6];
    const float* b3 = (const float*)d_in[7];
    float* out = (float*)d_out;

    float4 *bufA, *bufB;
    cudaGetSymbolAddress((void**)&bufA, g_bufA);
    cudaGetSymbolAddress((void**)&bufB, g_bufB);

    const dim3 blk(256);
    const dim3 gHid((DH + 63) / 64, (NN + 63) / 64);  // (4, 157)
    const dim3 gCls((NC + 63) / 64, (NN + 63) / 64);  // (1, 157)

    // Build CSR (dst-sorted) each launch: detect dtype, clean idx + zero deg,
    // histogram, scan, cursor fill.
    detect_dtype<<<1, 32>>>((const int*)ei);
    convert_idx<<<(2 * NE + 255) / 256, blk>>>(ei);
    hist_dst<<<(NE + 255) / 256, blk>>>();
    scan_deg<<<1, 1024>>>();
    fill_csr<<<(NE + 255) / 256, blk>>>();

    // Layer 1: h = x @ W1 + b1 ; agg (no atomics)
    gemm64<false><<<gHid, blk>>>(x, W1, b1, (float*)bufB, NN, DH, DH);
    agg256<<<NN, blk>>>((const float*)bufB, (float*)bufA);

    // Layer 2: h = relu(agg) @ W2 + b2 ; agg
    gemm64<true><<<gHid, blk>>>((const float*)bufA, W2, b2, (float*)bufB, NN, DH, DH);
    agg256<<<NN, blk>>>((const float*)bufB, (float*)bufA);

    // Layer 3: h = relu(agg) @ W3 + b3 ; out = relu(agg)
    gemm64<true><<<gCls, blk>>>((const float*)bufA, W3, b3, (float*)bufB, NN, NC, DH);
    agg40_relu<<<(NN + 3) / 4, blk>>>((const float*)bufB, out);
}

// round 6
// speedup vs baseline: 1.3399x; 1.1178x over previous
#include <cuda_runtime.h>

#define NN 10000
#define NE 320000
#define DH 256
#define NC 40

// Static scratch (allowed).
__device__ __align__(16) float4 g_bufA[NN * DH / 4];
__device__ __align__(16) float4 g_bufB[NN * DH / 4];
__device__ int g_idx[2 * NE];      // [0,NE)=src, [NE,2NE)=dst (clean int32)
__device__ int g_deg[NN];
__device__ int g_off[NN + 1];
__device__ int g_cur[NN];
__device__ int g_esrc[NE];         // src ids grouped by dst (CSR payload)
__device__ int g_is64;

// ---------------------------------------------------------------------------
// Edge-index dtype detection (int64 vs int32).
// ---------------------------------------------------------------------------
__global__ void detect_dtype(const int* __restrict__ p)
{
    if (blockIdx.x == 0 && threadIdx.x == 0) {
        int any_nonzero = 0;
        for (int i = 0; i < 64; i++)
            any_nonzero |= p[2 * i + 1];
        g_is64 = (any_nonzero == 0) ? 1 : 0;
    }
}

// Convert edge index to clean int32 (clamped) AND zero the degree histogram.
__global__ void convert_idx(const void* __restrict__ p)
{
    const int i = blockIdx.x * blockDim.x + threadIdx.x;
    if (i < NN) g_deg[i] = 0;
    if (i >= 2 * NE) return;
    int v;
    if (g_is64) v = (int)((const long long*)p)[i];
    else        v = ((const int*)p)[i];
    g_idx[i] = min(max(v, 0), NN - 1);
}

__global__ void hist_dst()
{
    const int e = blockIdx.x * blockDim.x + threadIdx.x;
    if (e < NE) atomicAdd(&g_deg[g_idx[NE + e]], 1);
}

// ---------------------------------------------------------------------------
// Fast single-block exclusive scan: 1024 threads x 10 elements each.
// Serial local sums + two warp-shuffle scans; 2 barriers total.
// ---------------------------------------------------------------------------
__global__ void scan_deg_fast()
{
    const int t = threadIdx.x;
    const int lane = t & 31, warp = t >> 5;
    const int base = t * 10;

    int lexcl[10];
    int sum = 0;
#pragma unroll
    for (int i = 0; i < 10; i++) {
        const int idx = base + i;
        const int v = (idx < NN) ? g_deg[idx] : 0;
        lexcl[i] = sum;
        sum += v;
    }

    // warp inclusive scan of per-thread sums
    int x = sum;
#pragma unroll
    for (int d = 1; d < 32; d <<= 1) {
        int y = __shfl_up_sync(0xffffffffu, x, d);
        if (lane >= d) x += y;
    }
    __shared__ int wsum[32];
    if (lane == 31) wsum[warp] = x;
    __syncthreads();
    if (warp == 0) {
        int w = wsum[lane];
#pragma unroll
        for (int d = 1; d < 32; d <<= 1) {
            int y = __shfl_up_sync(0xffffffffu, w, d);
            if (lane >= d) w += y;
        }
        wsum[lane] = w;
    }
    __syncthreads();

    const int texcl = (x - sum) + (warp ? wsum[warp - 1] : 0);
#pragma unroll
    for (int i = 0; i < 10; i++) {
        const int idx = base + i;
        if (idx < NN) {
            const int o = texcl + lexcl[i];
            g_off[idx] = o;
            g_cur[idx] = o;
        }
    }
    if (t == 1023) g_off[NN] = wsum[31];
}

__global__ void fill_csr()
{
    const int e = blockIdx.x * blockDim.x + threadIdx.x;
    if (e >= NE) return;
    const int dst = g_idx[NE + e];
    const int pos = atomicAdd(&g_cur[dst], 1);
    g_esrc[pos] = g_idx[e];
}

// ---------------------------------------------------------------------------
// Tiled SGEMM, software-pipelined: C = act(A) @ B + bias.
// 64x64 tile, BK=16, 256 threads, 4x4 per thread, float4 smem fragments.
// ---------------------------------------------------------------------------
template<bool RELU_IN>
__global__ void gemm64(const float* __restrict__ A, const float* __restrict__ B,
                       const float* __restrict__ bias, float* __restrict__ C,
                       int M, int N, int K)
{
    __shared__ float As[16][64];
    __shared__ float Bs[16][64];
    const int tid = threadIdx.x;
    const int ty = tid >> 4, tx = tid & 15;
    const int m0 = blockIdx.y * 64;
    const int n0 = blockIdx.x * 64;

    float acc[4][4];
#pragma unroll
    for (int i = 0; i < 4; i++)
#pragma unroll
        for (int j = 0; j < 4; j++) acc[i][j] = 0.f;

    const int la = tid * 4;
    const int ar = la >> 4, ac = la & 15;   // A-tile: row 0..63, col 0..15
    const int br = la >> 6, bc = la & 63;   // B-tile: row 0..15, col 0..63
    const int grow = m0 + ar;
    const int gcol = n0 + bc;

    // prefetch tile 0
    float4 va = make_float4(0.f, 0.f, 0.f, 0.f);
    if (grow < M)
        va = *reinterpret_cast<const float4*>(&A[(size_t)grow * K + ac]);
    float4 vb = make_float4(0.f, 0.f, 0.f, 0.f);
    if (gcol < N)
        vb = *reinterpret_cast<const float4*>(&B[(size_t)br * N + gcol]);

    for (int k0 = 0; k0 < K; k0 += 16) {
        float4 sa = va;
        if (RELU_IN) {
            sa.x = fmaxf(sa.x, 0.f); sa.y = fmaxf(sa.y, 0.f);
            sa.z = fmaxf(sa.z, 0.f); sa.w = fmaxf(sa.w, 0.f);
        }
        As[ac + 0][ar] = sa.x; As[ac + 1][ar] = sa.y;
        As[ac + 2][ar] = sa.z; As[ac + 3][ar] = sa.w;
        Bs[br][bc + 0] = vb.x; Bs[br][bc + 1] = vb.y;
        Bs[br][bc + 2] = vb.z; Bs[br][bc + 3] = vb.w;
        __syncthreads();

        // prefetch next tile while computing this one
        if (k0 + 16 < K) {
            va = make_float4(0.f, 0.f, 0.f, 0.f);
            if (grow < M)
                va = *reinterpret_cast<const float4*>(&A[(size_t)grow * K + k0 + 16 + ac]);
            vb = make_float4(0.f, 0.f, 0.f, 0.f);
            if (gcol < N)
                vb = *reinterpret_cast<const float4*>(&B[(size_t)(k0 + 16 + br) * N + gcol]);
        }

#pragma unroll
        for (int k = 0; k < 16; k++) {
            const float4 a4 = *reinterpret_cast<const float4*>(&As[k][ty * 4]);
            const float4 b4 = *reinterpret_cast<const float4*>(&Bs[k][tx * 4]);
            const float a[4] = {a4.x, a4.y, a4.z, a4.w};
            const float b[4] = {b4.x, b4.y, b4.z, b4.w};
#pragma unroll
            for (int i = 0; i < 4; i++)
#pragma unroll
                for (int j = 0; j < 4; j++)
                    acc[i][j] += a[i] * b[j];
        }
        __syncthreads();
    }

#pragma unroll
    for (int i = 0; i < 4; i++) {
        int row = m0 + ty * 4 + i;
        if (row >= M) continue;
#pragma unroll
        for (int j = 0; j < 4; j++) {
            int col = n0 + tx * 4 + j;
            if (col < N)
                C[(size_t)row * N + col] = acc[i][j] + bias[col];
        }
    }
}

// ---------------------------------------------------------------------------
// Pull-mode aggregation, D=256, vectorized: 4 nodes per 256-thread block,
// 64 threads per node, each thread owns one float4 column chunk (LDG.128).
// Edge ids read uniformly per node-group (L1 broadcast). No atomics.
// ---------------------------------------------------------------------------
__global__ void agg256v(const float4* __restrict__ h4, float4* __restrict__ out4)
{
    const int tid = threadIdx.x;
    const int node = blockIdx.x * 4 + (tid >> 6);
    const int f4 = tid & 63;
    if (node >= NN) return;
    const int beg = g_off[node], end = g_off[node + 1];

    float4 acc = make_float4(0.f, 0.f, 0.f, 0.f);
    int e = beg;
    for (; e + 4 <= end; e += 4) {
        const int s0 = g_esrc[e + 0], s1 = g_esrc[e + 1];
        const int s2 = g_esrc[e + 2], s3 = g_esrc[e + 3];
        const float4 v0 = h4[(size_t)s0 * 64 + f4];
        const float4 v1 = h4[(size_t)s1 * 64 + f4];
        const float4 v2 = h4[(size_t)s2 * 64 + f4];
        const float4 v3 = h4[(size_t)s3 * 64 + f4];
        acc.x += (v0.x + v1.x) + (v2.x + v3.x);
        acc.y += (v0.y + v1.y) + (v2.y + v3.y);
        acc.z += (v0.z + v1.z) + (v2.z + v3.z);
        acc.w += (v0.w + v1.w) + (v2.w + v3.w);
    }
    for (; e < end; e++) {
        const float4 v = h4[(size_t)g_esrc[e] * 64 + f4];
        acc.x += v.x; acc.y += v.y; acc.z += v.z; acc.w += v.w;
    }
    out4[(size_t)node * 64 + f4] = acc;
}

// ---------------------------------------------------------------------------
// Pull-mode aggregation, D=40 (+ReLU): 4 nodes per 256-thread block.
// ---------------------------------------------------------------------------
__global__ void agg40_relu(const float* __restrict__ h, float* __restrict__ out)
{
    const int tid = threadIdx.x;
    const int node = blockIdx.x * 4 + (tid >> 6);
    const int f = tid & 63;
    if (node >= NN || f >= NC) return;
    const int beg = g_off[node], end = g_off[node + 1];

    float acc = 0.f;
    int e = beg;
    for (; e + 4 <= end; e += 4) {
        const int s0 = g_esrc[e + 0], s1 = g_esrc[e + 1];
        const int s2 = g_esrc[e + 2], s3 = g_esrc[e + 3];
        const float v0 = h[(size_t)s0 * NC + f];
        const float v1 = h[(size_t)s1 * NC + f];
        const float v2 = h[(size_t)s2 * NC + f];
        const float v3 = h[(size_t)s3 * NC + f];
        acc += (v0 + v1) + (v2 + v3);
    }
    for (; e < end; e++)
        acc += h[(size_t)g_esrc[e] * NC + f];
    out[(size_t)node * NC + f] = fmaxf(acc, 0.f);
}

// ---------------------------------------------------------------------------
extern "C" void kernel_launch(void* const* d_in, const int* in_sizes, int n_in,
                              void* d_out, int out_size)
{
    const float* x  = (const float*)d_in[0];
    const void*  ei = d_in[1];
    const float* W1 = (const float*)d_in[2];
    const float* b1 = (const float*)d_in[3];
    const float* W2 = (const float*)d_in[4];
    const float* b2 = (const float*)d_in[5];
    const float* W3 = (const float*)d_in[6];
    const float* b3 = (const float*)d_in[7];
    float* out = (float*)d_out;

    float4 *bufA, *bufB;
    cudaGetSymbolAddress((void**)&bufA, g_bufA);
    cudaGetSymbolAddress((void**)&bufB, g_bufB);

    const dim3 blk(256);
    const dim3 gHid((DH + 63) / 64, (NN + 63) / 64);  // (4, 157)
    const dim3 gCls((NC + 63) / 64, (NN + 63) / 64);  // (1, 157)

    // Build CSR (dst-sorted) each launch.
    detect_dtype<<<1, 32>>>((const int*)ei);
    convert_idx<<<(2 * NE + 255) / 256, blk>>>(ei);
    hist_dst<<<(NE + 255) / 256, blk>>>();
    scan_deg_fast<<<1, 1024>>>();
    fill_csr<<<(NE + 255) / 256, blk>>>();

    // Layer 1: h = x @ W1 + b1 ; agg (no atomics)
    gemm64<false><<<gHid, blk>>>(x, W1, b1, (float*)bufB, NN, DH, DH);
    agg256v<<<(NN + 3) / 4, blk>>>(bufB, bufA);

    // Layer 2: h = relu(agg) @ W2 + b2 ; agg
    gemm64<true><<<gHid, blk>>>((const float*)bufA, W2, b2, (float*)bufB, NN, DH, DH);
    agg256v<<<(NN + 3) / 4, blk>>>(bufB, bufA);

    // Layer 3: h = relu(agg) @ W3 + b3 ; out = relu(agg)
    gemm64<true><<<gCls, blk>>>((const float*)bufA, W3, b3, (float*)bufB, NN, NC, DH);
    agg40_relu<<<(NN + 3) / 4, blk>>>((const float*)bufB, out);
}

// round 9
// speedup vs baseline: 1.4715x; 1.0982x over previous
#include <cuda_runtime.h>

#define NN 10000
#define NE 320000
#define DH 256
#define NC 40

// Static scratch (allowed).
__device__ __align__(16) float4 g_bufA[NN * DH / 4];
__device__ __align__(16) float4 g_bufB[NN * DH / 4];
__device__ int g_idx[2 * NE];      // [0,NE)=src, [NE,2NE)=dst (clean int32)
__device__ int g_deg[NN];
__device__ int g_off[NN + 1];
__device__ int g_cur[NN];
__device__ int g_esrc[NE];         // src ids grouped by dst (CSR payload)
__device__ int g_is64;

// ---------------------------------------------------------------------------
// Detect edge-index dtype (int64 vs int32) AND zero the degree histogram.
// For int64 values < 2^31 every odd int32 word is zero.
// ---------------------------------------------------------------------------
__global__ void detect_and_zero(const int* __restrict__ p)
{
    const int i = blockIdx.x * blockDim.x + threadIdx.x;
    if (i < NN) g_deg[i] = 0;
    if (i == 0) {
        int any_nonzero = 0;
        for (int k = 0; k < 64; k++)
            any_nonzero |= p[2 * k + 1];
        g_is64 = (any_nonzero == 0) ? 1 : 0;
    }
}

// Convert edge index to clean int32 (clamped) AND histogram dst inline.
__global__ void convert_hist(const void* __restrict__ p)
{
    const int i = blockIdx.x * blockDim.x + threadIdx.x;
    if (i >= 2 * NE) return;
    int v;
    if (g_is64) v = (int)((const long long*)p)[i];
    else        v = ((const int*)p)[i];
    v = min(max(v, 0), NN - 1);
    g_idx[i] = v;
    if (i >= NE) atomicAdd(&g_deg[v], 1);
}

// ---------------------------------------------------------------------------
// Single-block exclusive scan: 1024 threads x 10 elements each.
// ---------------------------------------------------------------------------
__global__ void scan_deg_fast()
{
    const int t = threadIdx.x;
    const int lane = t & 31, warp = t >> 5;
    const int base = t * 10;

    int lexcl[10];
    int sum = 0;
#pragma unroll
    for (int i = 0; i < 10; i++) {
        const int idx = base + i;
        const int v = (idx < NN) ? __ldg(&g_deg[idx]) : 0;
        lexcl[i] = sum;
        sum += v;
    }

    int x = sum;
#pragma unroll
    for (int d = 1; d < 32; d <<= 1) {
        int y = __shfl_up_sync(0xffffffffu, x, d);
        if (lane >= d) x += y;
    }
    __shared__ int wsum[32];
    if (lane == 31) wsum[warp] = x;
    __syncthreads();
    if (warp == 0) {
        int w = wsum[lane];
#pragma unroll
        for (int d = 1; d < 32; d <<= 1) {
            int y = __shfl_up_sync(0xffffffffu, w, d);
            if (lane >= d) w += y;
        }
        wsum[lane] = w;
    }
    __syncthreads();

    const int texcl = (x - sum) + (warp ? wsum[warp - 1] : 0);
#pragma unroll
    for (int i = 0; i < 10; i++) {
        const int idx = base + i;
        if (idx < NN) {
            const int o = texcl + lexcl[i];
            g_off[idx] = o;
            g_cur[idx] = o;
        }
    }
    if (t == 1023) g_off[NN] = wsum[31];
}

__global__ void fill_csr()
{
    const int e = blockIdx.x * blockDim.x + threadIdx.x;
    if (e >= NE) return;
    const int dst = g_idx[NE + e];
    const int pos = atomicAdd(&g_cur[dst], 1);
    g_esrc[pos] = g_idx[e];
}

// ---------------------------------------------------------------------------
// Tiled SGEMM, software-pipelined: C = act(A) @ B + bias.
// 64x64 tile, BK=16, 256 threads, 4x4 per thread, float4 smem fragments.
// ---------------------------------------------------------------------------
template<bool RELU_IN>
__global__ void gemm64(const float* __restrict__ A, const float* __restrict__ B,
                       const float* __restrict__ bias, float* __restrict__ C,
                       int M, int N, int K)
{
    __shared__ float As[16][64];
    __shared__ float Bs[16][64];
    const int tid = threadIdx.x;
    const int ty = tid >> 4, tx = tid & 15;
    const int m0 = blockIdx.y * 64;
    const int n0 = blockIdx.x * 64;

    float acc[4][4];
#pragma unroll
    for (int i = 0; i < 4; i++)
#pragma unroll
        for (int j = 0; j < 4; j++) acc[i][j] = 0.f;

    const int la = tid * 4;
    const int ar = la >> 4, ac = la & 15;
    const int br = la >> 6, bc = la & 63;
    const int grow = m0 + ar;
    const int gcol = n0 + bc;

    float4 va = make_float4(0.f, 0.f, 0.f, 0.f);
    if (grow < M)
        va = *reinterpret_cast<const float4*>(&A[(size_t)grow * K + ac]);
    float4 vb = make_float4(0.f, 0.f, 0.f, 0.f);
    if (gcol < N)
        vb = *reinterpret_cast<const float4*>(&B[(size_t)br * N + gcol]);

    for (int k0 = 0; k0 < K; k0 += 16) {
        float4 sa = va;
        if (RELU_IN) {
            sa.x = fmaxf(sa.x, 0.f); sa.y = fmaxf(sa.y, 0.f);
            sa.z = fmaxf(sa.z, 0.f); sa.w = fmaxf(sa.w, 0.f);
        }
        As[ac + 0][ar] = sa.x; As[ac + 1][ar] = sa.y;
        As[ac + 2][ar] = sa.z; As[ac + 3][ar] = sa.w;
        Bs[br][bc + 0] = vb.x; Bs[br][bc + 1] = vb.y;
        Bs[br][bc + 2] = vb.z; Bs[br][bc + 3] = vb.w;
        __syncthreads();

        if (k0 + 16 < K) {
            va = make_float4(0.f, 0.f, 0.f, 0.f);
            if (grow < M)
                va = *reinterpret_cast<const float4*>(&A[(size_t)grow * K + k0 + 16 + ac]);
            vb = make_float4(0.f, 0.f, 0.f, 0.f);
            if (gcol < N)
                vb = *reinterpret_cast<const float4*>(&B[(size_t)(k0 + 16 + br) * N + gcol]);
        }

#pragma unroll
        for (int k = 0; k < 16; k++) {
            const float4 a4 = *reinterpret_cast<const float4*>(&As[k][ty * 4]);
            const float4 b4 = *reinterpret_cast<const float4*>(&Bs[k][tx * 4]);
            const float a[4] = {a4.x, a4.y, a4.z, a4.w};
            const float b[4] = {b4.x, b4.y, b4.z, b4.w};
#pragma unroll
            for (int i = 0; i < 4; i++)
#pragma unroll
                for (int j = 0; j < 4; j++)
                    acc[i][j] += a[i] * b[j];
        }
        __syncthreads();
    }

#pragma unroll
    for (int i = 0; i < 4; i++) {
        int row = m0 + ty * 4 + i;
        if (row >= M) continue;
#pragma unroll
        for (int j = 0; j < 4; j++) {
            int col = n0 + tx * 4 + j;
            if (col < N)
                C[(size_t)row * N + col] = acc[i][j] + bias[col];
        }
    }
}

// ---------------------------------------------------------------------------
// Pull-mode aggregation, D=256, vectorized: 4 nodes per 256-thread block,
// 64 threads per node, float4 per thread (LDG.128). No atomics.
// ---------------------------------------------------------------------------
__global__ void agg256v(const float4* __restrict__ h4, float4* __restrict__ out4)
{
    const int tid = threadIdx.x;
    const int node = blockIdx.x * 4 + (tid >> 6);
    const int f4 = tid & 63;
    if (node >= NN) return;
    const int beg = g_off[node], end = g_off[node + 1];

    float4 acc = make_float4(0.f, 0.f, 0.f, 0.f);
    int e = beg;
    for (; e + 4 <= end; e += 4) {
        const int s0 = g_esrc[e + 0], s1 = g_esrc[e + 1];
        const int s2 = g_esrc[e + 2], s3 = g_esrc[e + 3];
        const float4 v0 = h4[(size_t)s0 * 64 + f4];
        const float4 v1 = h4[(size_t)s1 * 64 + f4];
        const float4 v2 = h4[(size_t)s2 * 64 + f4];
        const float4 v3 = h4[(size_t)s3 * 64 + f4];
        acc.x += (v0.x + v1.x) + (v2.x + v3.x);
        acc.y += (v0.y + v1.y) + (v2.y + v3.y);
        acc.z += (v0.z + v1.z) + (v2.z + v3.z);
        acc.w += (v0.w + v1.w) + (v2.w + v3.w);
    }
    for (; e < end; e++) {
        const float4 v = h4[(size_t)g_esrc[e] * 64 + f4];
        acc.x += v.x; acc.y += v.y; acc.z += v.z; acc.w += v.w;
    }
    out4[(size_t)node * 64 + f4] = acc;
}

// ---------------------------------------------------------------------------
// Pull-mode aggregation, D=40 (+ReLU): 4 nodes per 256-thread block.
// ---------------------------------------------------------------------------
__global__ void agg40_relu(const float* __restrict__ h, float* __restrict__ out)
{
    const int tid = threadIdx.x;
    const int node = blockIdx.x * 4 + (tid >> 6);
    const int f = tid & 63;
    if (node >= NN || f >= NC) return;
    const int beg = g_off[node], end = g_off[node + 1];

    float acc = 0.f;
    int e = beg;
    for (; e + 4 <= end; e += 4) {
        const int s0 = g_esrc[e + 0], s1 = g_esrc[e + 1];
        const int s2 = g_esrc[e + 2], s3 = g_esrc[e + 3];
        const float v0 = h[(size_t)s0 * NC + f];
        const float v1 = h[(size_t)s1 * NC + f];
        const float v2 = h[(size_t)s2 * NC + f];
        const float v3 = h[(size_t)s3 * NC + f];
        acc += (v0 + v1) + (v2 + v3);
    }
    for (; e < end; e++)
        acc += h[(size_t)g_esrc[e] * NC + f];
    out[(size_t)node * NC + f] = fmaxf(acc, 0.f);
}

// ---------------------------------------------------------------------------
extern "C" void kernel_launch(void* const* d_in, const int* in_sizes, int n_in,
                              void* d_out, int out_size)
{
    const float* x  = (const float*)d_in[0];
    const void*  ei = d_in[1];
    const float* W1 = (const float*)d_in[2];
    const float* b1 = (const float*)d_in[3];
    const float* W2 = (const float*)d_in[4];
    const float* b2 = (const float*)d_in[5];
    const float* W3 = (const float*)d_in[6];
    const float* b3 = (const float*)d_in[7];
    float* out = (float*)d_out;

    float4 *bufA, *bufB;
    cudaGetSymbolAddress((void**)&bufA, g_bufA);
    cudaGetSymbolAddress((void**)&bufB, g_bufB);

    // Lazy host-side objects (no device memory involved; identical GPU work
    // and graph topology on every call).
    static cudaStream_t s_side = nullptr;
    static cudaEvent_t ev_fork = nullptr, ev_join = nullptr;
    if (s_side == nullptr) {
        cudaStreamCreateWithFlags(&s_side, cudaStreamNonBlocking);
        cudaEventCreateWithFlags(&ev_fork, cudaEventDisableTiming);
        cudaEventCreateWithFlags(&ev_join, cudaEventDisableTiming);
    }

    const dim3 blk(256);
    const dim3 gHid((DH + 63) / 64, (NN + 63) / 64);  // (4, 157)
    const dim3 gCls((NC + 63) / 64, (NN + 63) / 64);  // (1, 157)

    // Fork: CSR build on side stream, layer-1 GEMM on main stream.
    cudaEventRecord(ev_fork, 0);
    cudaStreamWaitEvent(s_side, ev_fork, 0);

    detect_and_zero<<<(NN + 255) / 256, blk, 0, s_side>>>((const int*)ei);
    convert_hist<<<(2 * NE + 255) / 256, blk, 0, s_side>>>(ei);
    scan_deg_fast<<<1, 1024, 0, s_side>>>();
    fill_csr<<<(NE + 255) / 256, blk, 0, s_side>>>();
    cudaEventRecord(ev_join, s_side);

    // Layer 1 GEMM overlaps the CSR build.
    gemm64<false><<<gHid, blk>>>(x, W1, b1, (float*)bufB, NN, DH, DH);

    // Join: aggregation needs both GEMM1 output and the CSR.
    cudaStreamWaitEvent(0, ev_join, 0);
    agg256v<<<(NN + 3) / 4, blk>>>(bufB, bufA);

    // Layer 2
    gemm64<true><<<gHid, blk>>>((const float*)bufA, W2, b2, (float*)bufB, NN, DH, DH);
    agg256v<<<(NN + 3) / 4, blk>>>(bufB, bufA);

    // Layer 3
    gemm64<true><<<gCls, blk>>>((const float*)bufA, W3, b3, (float*)bufB, NN, NC, DH);
    agg40_relu<<<(NN + 3) / 4, blk>>>((const float*)bufB, out);
}